// round 3
// baseline (speedup 1.0000x reference)
#include <cuda_runtime.h>

typedef unsigned long long u64;

#define NN 100000
#define NE 1600000
#define EMBD 128
#define G1D 512
#define G2D 64000
#define DD 64
#define ECD 16
#define NB 100

// ---------------- scratch (device globals; no allocation) ----------------
__device__ float g_h[NB * G1D];
__device__ float g_x[NN * DD];
__device__ float g_x2[NN * DD];
__device__ float g_y[NN * DD];
__device__ float g_agg[NN * DD];

// ---------------- packed f32x2 helpers ----------------
__device__ __forceinline__ u64 f2fma(u64 a, u64 b, u64 c) {
    u64 d;
    asm("fma.rn.f32x2 %0, %1, %2, %3;" : "=l"(d) : "l"(a), "l"(b), "l"(c));
    return d;
}
__device__ __forceinline__ u64 f2dup(float x) {
    u64 d;
    asm("mov.b64 %0, {%1, %2};" : "=l"(d) : "f"(x), "f"(x));
    return d;
}
__device__ __forceinline__ float2 f2unpack(u64 d) {
    float2 r;
    asm("mov.b64 {%0, %1}, %2;" : "=f"(r.x), "=f"(r.y) : "l"(d));
    return r;
}

// ---------------- mlp1: h = relu(emb @ Wg1 + bg1) ----------------
__global__ __launch_bounds__(512) void k_mlp1(const float* __restrict__ emb,
                                              const float* __restrict__ W,
                                              const float* __restrict__ b) {
    __shared__ float sE[EMBD];
    int bid = blockIdx.x, tid = threadIdx.x;
    if (tid < EMBD) sE[tid] = emb[bid * EMBD + tid];
    __syncthreads();
    float acc = 0.f;
#pragma unroll 16
    for (int k = 0; k < EMBD; k++) acc += sE[k] * __ldg(&W[k * G1D + tid]);
    g_h[bid * G1D + tid] = fmaxf(acc + b[tid], 0.f);
}

// ---------------- mlp2: x = h @ Wg2 + bg2 ([100,512]@[512,64000]) ----------------
__global__ __launch_bounds__(256) void k_mlp2(const float* __restrict__ W,
                                              const float* __restrict__ bias) {
    __shared__ __align__(16) u64 sA[16][128];
    __shared__ __align__(16) float sB[16][128];
    const float* h = g_h;
    int tid = threadIdx.x;
    int n0 = blockIdx.x * 128;
    int tx = tid & 15, ty = tid >> 4;
    int mb = ty * 8, cb = tx * 8;
    u64 acc[8][4];
#pragma unroll
    for (int r = 0; r < 8; r++)
#pragma unroll
        for (int c = 0; c < 4; c++) acc[r][c] = 0ull;

    int am = tid >> 1;
    int ak = (tid & 1) * 8;
    int bk = tid >> 4;
    int bn = (tid & 15) * 8;

    for (int k0 = 0; k0 < G1D; k0 += 16) {
        float4 a0 = make_float4(0.f, 0.f, 0.f, 0.f), a1 = a0;
        if (am < NB) {
            const float4* hp = reinterpret_cast<const float4*>(h + am * G1D + k0 + ak);
            a0 = hp[0];
            a1 = hp[1];
        }
        const float4* wp =
            reinterpret_cast<const float4*>(W + (u64)(k0 + bk) * G2D + n0 + bn);
        float4 b0 = wp[0], b1 = wp[1];
        __syncthreads();
        sA[ak + 0][am] = f2dup(a0.x);
        sA[ak + 1][am] = f2dup(a0.y);
        sA[ak + 2][am] = f2dup(a0.z);
        sA[ak + 3][am] = f2dup(a0.w);
        sA[ak + 4][am] = f2dup(a1.x);
        sA[ak + 5][am] = f2dup(a1.y);
        sA[ak + 6][am] = f2dup(a1.z);
        sA[ak + 7][am] = f2dup(a1.w);
        *reinterpret_cast<float4*>(&sB[bk][bn]) = b0;
        *reinterpret_cast<float4*>(&sB[bk][bn + 4]) = b1;
        __syncthreads();
#pragma unroll
        for (int k = 0; k < 16; k++) {
            const ulonglong2* ap = reinterpret_cast<const ulonglong2*>(&sA[k][mb]);
            ulonglong2 av0 = ap[0], av1 = ap[1], av2 = ap[2], av3 = ap[3];
            const ulonglong2* bp = reinterpret_cast<const ulonglong2*>(&sB[k][cb]);
            ulonglong2 bv0 = bp[0], bv1 = bp[1];
            u64 ar[8] = {av0.x, av0.y, av1.x, av1.y, av2.x, av2.y, av3.x, av3.y};
            u64 br[4] = {bv0.x, bv0.y, bv1.x, bv1.y};
#pragma unroll
            for (int r = 0; r < 8; r++)
#pragma unroll
                for (int c = 0; c < 4; c++) acc[r][c] = f2fma(ar[r], br[c], acc[r][c]);
        }
    }
    float2 bs[4];
#pragma unroll
    for (int c = 0; c < 4; c++)
        bs[c] = *reinterpret_cast<const float2*>(bias + n0 + cb + 2 * c);
#pragma unroll
    for (int r = 0; r < 8; r++) {
        int row = mb + r;
        if (row < NB) {
            float* op = g_x + (u64)row * G2D + n0 + cb;
#pragma unroll
            for (int c = 0; c < 4; c++) {
                float2 v = f2unpack(acc[r][c]);
                v.x += bs[c].x;
                v.y += bs[c].y;
                *reinterpret_cast<float2*>(op + 2 * c) = v;
            }
        }
    }
}

// ---------------- y = x @ mW[0:64] + mb; zero agg ----------------
__global__ __launch_bounds__(256) void k_ynode(const float* __restrict__ x,
                                               const float* __restrict__ mW,
                                               const float* __restrict__ mb) {
    __shared__ __align__(16) float sX[32][64];
    __shared__ __align__(16) float sW[64][64];
    int tid = threadIdx.x;
    int node0 = blockIdx.x * 32;
    for (int i = tid; i < 64 * 64; i += 256) sW[i >> 6][i & 63] = mW[i];
    int nl = tid >> 3, f0 = (tid & 7) * 8;
    {
        const float4* xp = reinterpret_cast<const float4*>(x + (u64)(node0 + nl) * DD + f0);
        *reinterpret_cast<float4*>(&sX[nl][f0]) = xp[0];
        *reinterpret_cast<float4*>(&sX[nl][f0 + 4]) = xp[1];
    }
    __syncthreads();
    u64 acc[4] = {0ull, 0ull, 0ull, 0ull};
#pragma unroll
    for (int k = 0; k < 64; k++) {
        u64 ad = f2dup(sX[nl][k]);
        const ulonglong2* wp = reinterpret_cast<const ulonglong2*>(&sW[k][f0]);
        ulonglong2 w0 = wp[0], w1 = wp[1];
        acc[0] = f2fma(ad, w0.x, acc[0]);
        acc[1] = f2fma(ad, w0.y, acc[1]);
        acc[2] = f2fma(ad, w1.x, acc[2]);
        acc[3] = f2fma(ad, w1.y, acc[3]);
    }
    float o[8];
#pragma unroll
    for (int c = 0; c < 4; c++) {
        float2 v = f2unpack(acc[c]);
        o[2 * c] = v.x + mb[f0 + 2 * c];
        o[2 * c + 1] = v.y + mb[f0 + 2 * c + 1];
    }
    float* yp = g_y + (u64)(node0 + nl) * DD + f0;
    *reinterpret_cast<float4*>(yp) = make_float4(o[0], o[1], o[2], o[3]);
    *reinterpret_cast<float4*>(yp + 4) = make_float4(o[4], o[5], o[6], o[7]);
    float* ap = g_agg + (u64)(node0 + nl) * DD + f0;
    *reinterpret_cast<float4*>(ap) = make_float4(0.f, 0.f, 0.f, 0.f);
    *reinterpret_cast<float4*>(ap + 4) = make_float4(0.f, 0.f, 0.f, 0.f);
}

// ---------------- edge: agg[dst] += relu(y[src] + ea @ mW[64:80]) ----------------
__global__ __launch_bounds__(256) void k_edge(const float* __restrict__ ea,
                                              const int* __restrict__ ei,
                                              const float* __restrict__ mW) {
    __shared__ __align__(16) float sW[16][64];
    int tid = threadIdx.x;
    for (int i = tid; i < 16 * 64; i += 256) sW[i >> 6][i & 63] = mW[64 * DD + i];
    __syncthreads();
    int e = blockIdx.x * 64 + (tid >> 2);
    int c0 = (tid & 3) * 16;
    int src = __ldg(&ei[e]);
    int dst = __ldg(&ei[NE + e]);
    const float4* ep = reinterpret_cast<const float4*>(ea + (u64)e * ECD);
    float4 e0 = ep[0], e1 = ep[1], e2 = ep[2], e3 = ep[3];
    u64 ed[16];
    ed[0] = f2dup(e0.x); ed[1] = f2dup(e0.y); ed[2] = f2dup(e0.z); ed[3] = f2dup(e0.w);
    ed[4] = f2dup(e1.x); ed[5] = f2dup(e1.y); ed[6] = f2dup(e1.z); ed[7] = f2dup(e1.w);
    ed[8] = f2dup(e2.x); ed[9] = f2dup(e2.y); ed[10] = f2dup(e2.z); ed[11] = f2dup(e2.w);
    ed[12] = f2dup(e3.x); ed[13] = f2dup(e3.y); ed[14] = f2dup(e3.z); ed[15] = f2dup(e3.w);
    u64 acc[8];
#pragma unroll
    for (int i = 0; i < 8; i++) acc[i] = 0ull;
#pragma unroll
    for (int k = 0; k < 16; k++) {
        const ulonglong2* wp = reinterpret_cast<const ulonglong2*>(&sW[k][c0]);
        ulonglong2 w0 = wp[0], w1 = wp[1], w2 = wp[2], w3 = wp[3];
        acc[0] = f2fma(ed[k], w0.x, acc[0]);
        acc[1] = f2fma(ed[k], w0.y, acc[1]);
        acc[2] = f2fma(ed[k], w1.x, acc[2]);
        acc[3] = f2fma(ed[k], w1.y, acc[3]);
        acc[4] = f2fma(ed[k], w2.x, acc[4]);
        acc[5] = f2fma(ed[k], w2.y, acc[5]);
        acc[6] = f2fma(ed[k], w3.x, acc[6]);
        acc[7] = f2fma(ed[k], w3.y, acc[7]);
    }
    const float4* yp = reinterpret_cast<const float4*>(g_y + (u64)src * DD + c0);
    float4 y0 = yp[0], y1 = yp[1], y2 = yp[2], y3 = yp[3];
    float m[16];
    float2 v;
    v = f2unpack(acc[0]); m[0] = fmaxf(y0.x + v.x, 0.f); m[1] = fmaxf(y0.y + v.y, 0.f);
    v = f2unpack(acc[1]); m[2] = fmaxf(y0.z + v.x, 0.f); m[3] = fmaxf(y0.w + v.y, 0.f);
    v = f2unpack(acc[2]); m[4] = fmaxf(y1.x + v.x, 0.f); m[5] = fmaxf(y1.y + v.y, 0.f);
    v = f2unpack(acc[3]); m[6] = fmaxf(y1.z + v.x, 0.f); m[7] = fmaxf(y1.w + v.y, 0.f);
    v = f2unpack(acc[4]); m[8] = fmaxf(y2.x + v.x, 0.f); m[9] = fmaxf(y2.y + v.y, 0.f);
    v = f2unpack(acc[5]); m[10] = fmaxf(y2.z + v.x, 0.f); m[11] = fmaxf(y2.w + v.y, 0.f);
    v = f2unpack(acc[6]); m[12] = fmaxf(y3.x + v.x, 0.f); m[13] = fmaxf(y3.y + v.y, 0.f);
    v = f2unpack(acc[7]); m[14] = fmaxf(y3.z + v.x, 0.f); m[15] = fmaxf(y3.w + v.y, 0.f);
    float* ap = g_agg + (u64)dst * DD + c0;
    asm volatile("red.global.add.v4.f32 [%0], {%1,%2,%3,%4};" ::"l"(ap),
                 "f"(m[0]), "f"(m[1]), "f"(m[2]), "f"(m[3]) : "memory");
    asm volatile("red.global.add.v4.f32 [%0], {%1,%2,%3,%4};" ::"l"(ap + 4),
                 "f"(m[4]), "f"(m[5]), "f"(m[6]), "f"(m[7]) : "memory");
    asm volatile("red.global.add.v4.f32 [%0], {%1,%2,%3,%4};" ::"l"(ap + 8),
                 "f"(m[8]), "f"(m[9]), "f"(m[10]), "f"(m[11]) : "memory");
    asm volatile("red.global.add.v4.f32 [%0], {%1,%2,%3,%4};" ::"l"(ap + 12),
                 "f"(m[12]), "f"(m[13]), "f"(m[14]), "f"(m[15]) : "memory");
}

// ---------------- update: xo = relu([x, agg] @ uW + ub) ----------------
__global__ __launch_bounds__(128) void k_update(const float* __restrict__ x,
                                                const float* __restrict__ uW,
                                                const float* __restrict__ ub,
                                                float* __restrict__ xo) {
    __shared__ __align__(16) float sIn[16][128];
    __shared__ __align__(16) float sW[128][64];
    int tid = threadIdx.x;
    int node0 = blockIdx.x * 16;
    for (int i = tid; i < 128 * 64; i += 128) sW[i >> 6][i & 63] = uW[i];
    int nl = tid >> 3, f0 = (tid & 7) * 8;
    {
        const float4* xp = reinterpret_cast<const float4*>(x + (u64)(node0 + nl) * DD + f0);
        *reinterpret_cast<float4*>(&sIn[nl][f0]) = xp[0];
        *reinterpret_cast<float4*>(&sIn[nl][f0 + 4]) = xp[1];
        const float4* gp =
            reinterpret_cast<const float4*>(g_agg + (u64)(node0 + nl) * DD + f0);
        *reinterpret_cast<float4*>(&sIn[nl][64 + f0]) = gp[0];
        *reinterpret_cast<float4*>(&sIn[nl][64 + f0 + 4]) = gp[1];
    }
    __syncthreads();
    u64 acc[4] = {0ull, 0ull, 0ull, 0ull};
#pragma unroll 32
    for (int k = 0; k < 128; k++) {
        u64 ad = f2dup(sIn[nl][k]);
        const ulonglong2* wp = reinterpret_cast<const ulonglong2*>(&sW[k][f0]);
        ulonglong2 w0 = wp[0], w1 = wp[1];
        acc[0] = f2fma(ad, w0.x, acc[0]);
        acc[1] = f2fma(ad, w0.y, acc[1]);
        acc[2] = f2fma(ad, w1.x, acc[2]);
        acc[3] = f2fma(ad, w1.y, acc[3]);
    }
    float o[8];
#pragma unroll
    for (int c = 0; c < 4; c++) {
        float2 v = f2unpack(acc[c]);
        o[2 * c] = fmaxf(v.x + ub[f0 + 2 * c], 0.f);
        o[2 * c + 1] = fmaxf(v.y + ub[f0 + 2 * c + 1], 0.f);
    }
    float* op = xo + (u64)(node0 + nl) * DD + f0;
    *reinterpret_cast<float4*>(op) = make_float4(o[0], o[1], o[2], o[3]);
    *reinterpret_cast<float4*>(op + 4) = make_float4(o[4], o[5], o[6], o[7]);
}

// ---------------- node mlp: out = relu(x @ nW1 + nb1) @ nW2 + nb2 ----------------
__global__ __launch_bounds__(128) void k_nodemlp(const float* __restrict__ W1,
                                                 const float* __restrict__ b1,
                                                 const float* __restrict__ W2,
                                                 const float* __restrict__ b2,
                                                 float* __restrict__ out) {
    __shared__ __align__(16) float sW1[64][128];  // 32KB
    __shared__ float sW2[128][3];
    __shared__ __align__(16) float sX[16][64];  // 4KB
    __shared__ float sH[16][128];               // 8KB
    int tid = threadIdx.x;
    int node0 = blockIdx.x * 16;
    for (int i = tid; i < 64 * 128; i += 128) sW1[i >> 7][i & 127] = W1[i];
    sW2[tid][0] = W2[tid * 3 + 0];
    sW2[tid][1] = W2[tid * 3 + 1];
    sW2[tid][2] = W2[tid * 3 + 2];
    {
        int nl = tid >> 3, f0 = (tid & 7) * 8;
        const float4* xp =
            reinterpret_cast<const float4*>(g_x + (u64)(node0 + nl) * DD + f0);
        *reinterpret_cast<float4*>(&sX[nl][f0]) = xp[0];
        *reinterpret_cast<float4*>(&sX[nl][f0 + 4]) = xp[1];
    }
    __syncthreads();
    float bb = b1[tid];
#pragma unroll 4
    for (int n = 0; n < 16; n++) {
        float acc = bb;
#pragma unroll
        for (int k = 0; k < 64; k++) acc += sX[n][k] * sW1[k][tid];
        sH[n][tid] = fmaxf(acc, 0.f);
    }
    __syncthreads();
    if (tid < 48) {
        int node = tid / 3, c = tid % 3;
        float o = b2[c];
#pragma unroll 16
        for (int j = 0; j < 128; j++) o += sH[node][j] * sW2[j][c];
        out[(u64)(node0 + node) * 3 + c] = o;
    }
}

extern "C" void kernel_launch(void* const* d_in, const int* in_sizes, int n_in,
                              void* d_out, int out_size) {
    const float* emb = (const float*)d_in[0];
    const int* edge_index = (const int*)d_in[1];  // JAX x64-disabled: int32!
    const float* edge_attr = (const float*)d_in[2];
    const float* Wg1 = (const float*)d_in[3];
    const float* bg1 = (const float*)d_in[4];
    const float* Wg2 = (const float*)d_in[5];
    const float* bg2 = (const float*)d_in[6];
    const float* mW0 = (const float*)d_in[7];
    const float* mb0 = (const float*)d_in[8];
    const float* uW0 = (const float*)d_in[9];
    const float* ub0 = (const float*)d_in[10];
    const float* mW1 = (const float*)d_in[11];
    const float* mb1 = (const float*)d_in[12];
    const float* uW1 = (const float*)d_in[13];
    const float* ub1 = (const float*)d_in[14];
    const float* nW1 = (const float*)d_in[15];
    const float* nb1 = (const float*)d_in[16];
    const float* nW2 = (const float*)d_in[17];
    const float* nb2 = (const float*)d_in[18];
    float* out = (float*)d_out;

    float *p_x, *p_x2;
    cudaGetSymbolAddress((void**)&p_x, g_x);
    cudaGetSymbolAddress((void**)&p_x2, g_x2);

    k_mlp1<<<NB, 512>>>(emb, Wg1, bg1);
    k_mlp2<<<G2D / 128, 256>>>(Wg2, bg2);
    // GNN layer 0: g_x -> g_x2
    k_ynode<<<NN / 32, 256>>>(p_x, mW0, mb0);
    k_edge<<<NE / 64, 256>>>(edge_attr, edge_index, mW0);
    k_update<<<NN / 16, 128>>>(p_x, uW0, ub0, p_x2);
    // GNN layer 1: g_x2 -> g_x
    k_ynode<<<NN / 32, 256>>>(p_x2, mW1, mb1);
    k_edge<<<NE / 64, 256>>>(edge_attr, edge_index, mW1);
    k_update<<<NN / 16, 128>>>(p_x2, uW1, ub1, p_x);
    // node MLP
    k_nodemlp<<<NN / 16, 128>>>(nW1, nb1, nW2, nb2, out);
}

// round 4
// speedup vs baseline: 1.0764x; 1.0764x over previous
#include <cuda_runtime.h>

typedef unsigned long long u64;

#define NN 100000
#define NE 1600000
#define EMBD 128
#define G1D 512
#define G2D 64000
#define DD 64
#define ECD 16
#define NB 100
#define NSCAN_BLKS 196  // ceil(NN/512)

// ---------------- scratch (device globals; no allocation) ----------------
__device__ float g_h[NB * G1D];
__device__ float g_x[NN * DD];
__device__ float g_x2[NN * DD];
__device__ float g_y[NN * DD];
__device__ float g_agg[NN * DD];
__device__ int g_cnt[NN];
__device__ int g_rowptr[NN + 1];
__device__ int g_ofs[NN];
__device__ int g_bsum[NSCAN_BLKS];
__device__ int g_perm[NE];

// ---------------- packed f32x2 helpers ----------------
__device__ __forceinline__ u64 f2fma(u64 a, u64 b, u64 c) {
    u64 d;
    asm("fma.rn.f32x2 %0, %1, %2, %3;" : "=l"(d) : "l"(a), "l"(b), "l"(c));
    return d;
}
__device__ __forceinline__ u64 f2dup(float x) {
    u64 d;
    asm("mov.b64 %0, {%1, %2};" : "=l"(d) : "f"(x), "f"(x));
    return d;
}
__device__ __forceinline__ u64 f2pack(float x, float y) {
    u64 d;
    asm("mov.b64 %0, {%1, %2};" : "=l"(d) : "f"(x), "f"(y));
    return d;
}
__device__ __forceinline__ float2 f2unpack(u64 d) {
    float2 r;
    asm("mov.b64 {%0, %1}, %2;" : "=f"(r.x), "=f"(r.y) : "l"(d));
    return r;
}

// ---------------- mlp1: h = relu(emb @ Wg1 + bg1) ----------------
__global__ __launch_bounds__(512) void k_mlp1(const float* __restrict__ emb,
                                              const float* __restrict__ W,
                                              const float* __restrict__ b) {
    __shared__ float sE[EMBD];
    int bid = blockIdx.x, tid = threadIdx.x;
    if (tid < EMBD) sE[tid] = emb[bid * EMBD + tid];
    __syncthreads();
    float acc = 0.f;
#pragma unroll 16
    for (int k = 0; k < EMBD; k++) acc += sE[k] * __ldg(&W[k * G1D + tid]);
    g_h[bid * G1D + tid] = fmaxf(acc + b[tid], 0.f);
}

// ---------------- mlp2: x = h @ Wg2 + bg2 ([100,512]@[512,64000]) ----------------
__global__ __launch_bounds__(256) void k_mlp2(const float* __restrict__ W,
                                              const float* __restrict__ bias) {
    __shared__ __align__(16) u64 sA[16][128];
    __shared__ __align__(16) float sB[16][128];
    const float* h = g_h;
    int tid = threadIdx.x;
    int n0 = blockIdx.x * 128;
    int tx = tid & 15, ty = tid >> 4;
    int mb = ty * 8, cb = tx * 8;
    u64 acc[8][4];
#pragma unroll
    for (int r = 0; r < 8; r++)
#pragma unroll
        for (int c = 0; c < 4; c++) acc[r][c] = 0ull;

    int am = tid >> 1;
    int ak = (tid & 1) * 8;
    int bk = tid >> 4;
    int bn = (tid & 15) * 8;

    for (int k0 = 0; k0 < G1D; k0 += 16) {
        float4 a0 = make_float4(0.f, 0.f, 0.f, 0.f), a1 = a0;
        if (am < NB) {
            const float4* hp = reinterpret_cast<const float4*>(h + am * G1D + k0 + ak);
            a0 = hp[0];
            a1 = hp[1];
        }
        const float4* wp =
            reinterpret_cast<const float4*>(W + (u64)(k0 + bk) * G2D + n0 + bn);
        float4 b0 = wp[0], b1 = wp[1];
        __syncthreads();
        sA[ak + 0][am] = f2dup(a0.x);
        sA[ak + 1][am] = f2dup(a0.y);
        sA[ak + 2][am] = f2dup(a0.z);
        sA[ak + 3][am] = f2dup(a0.w);
        sA[ak + 4][am] = f2dup(a1.x);
        sA[ak + 5][am] = f2dup(a1.y);
        sA[ak + 6][am] = f2dup(a1.z);
        sA[ak + 7][am] = f2dup(a1.w);
        *reinterpret_cast<float4*>(&sB[bk][bn]) = b0;
        *reinterpret_cast<float4*>(&sB[bk][bn + 4]) = b1;
        __syncthreads();
#pragma unroll
        for (int k = 0; k < 16; k++) {
            const ulonglong2* ap = reinterpret_cast<const ulonglong2*>(&sA[k][mb]);
            ulonglong2 av0 = ap[0], av1 = ap[1], av2 = ap[2], av3 = ap[3];
            const ulonglong2* bp = reinterpret_cast<const ulonglong2*>(&sB[k][cb]);
            ulonglong2 bv0 = bp[0], bv1 = bp[1];
            u64 ar[8] = {av0.x, av0.y, av1.x, av1.y, av2.x, av2.y, av3.x, av3.y};
            u64 br[4] = {bv0.x, bv0.y, bv1.x, bv1.y};
#pragma unroll
            for (int r = 0; r < 8; r++)
#pragma unroll
                for (int c = 0; c < 4; c++) acc[r][c] = f2fma(ar[r], br[c], acc[r][c]);
        }
    }
    float2 bs[4];
#pragma unroll
    for (int c = 0; c < 4; c++)
        bs[c] = *reinterpret_cast<const float2*>(bias + n0 + cb + 2 * c);
#pragma unroll
    for (int r = 0; r < 8; r++) {
        int row = mb + r;
        if (row < NB) {
            float* op = g_x + (u64)row * G2D + n0 + cb;
#pragma unroll
            for (int c = 0; c < 4; c++) {
                float2 v = f2unpack(acc[r][c]);
                v.x += bs[c].x;
                v.y += bs[c].y;
                *reinterpret_cast<float2*>(op + 2 * c) = v;
            }
        }
    }
}

// ---------------- CSR build: histogram + scan + permutation ----------------
__global__ void k_zero_cnt() {
    int i = blockIdx.x * 256 + threadIdx.x;
    if (i < NN) g_cnt[i] = 0;
}

__global__ void k_hist(const int* __restrict__ ei) {
    int e = blockIdx.x * 256 + threadIdx.x;
    if (e < NE) atomicAdd(&g_cnt[__ldg(&ei[NE + e])], 1);
}

__global__ __launch_bounds__(512) void k_scan1() {
    __shared__ int s[512];
    int i = blockIdx.x * 512 + threadIdx.x;
    int v = (i < NN) ? g_cnt[i] : 0;
    s[threadIdx.x] = v;
    __syncthreads();
#pragma unroll
    for (int off = 1; off < 512; off <<= 1) {
        int t = (threadIdx.x >= off) ? s[threadIdx.x - off] : 0;
        __syncthreads();
        s[threadIdx.x] += t;
        __syncthreads();
    }
    if (i < NN) g_rowptr[i] = s[threadIdx.x] - v;  // exclusive within block
    if (threadIdx.x == 511) g_bsum[blockIdx.x] = s[511];
}

__global__ __launch_bounds__(256) void k_scan2() {
    __shared__ int s[256];
    int tid = threadIdx.x;
    int v = (tid < NSCAN_BLKS) ? g_bsum[tid] : 0;
    s[tid] = v;
    __syncthreads();
#pragma unroll
    for (int off = 1; off < 256; off <<= 1) {
        int t = (tid >= off) ? s[tid - off] : 0;
        __syncthreads();
        s[tid] += t;
        __syncthreads();
    }
    if (tid < NSCAN_BLKS) g_bsum[tid] = s[tid] - v;  // exclusive block offsets
}

__global__ void k_scan3() {
    int i = blockIdx.x * 256 + threadIdx.x;
    if (i < NN) {
        int r = g_rowptr[i] + g_bsum[i >> 9];
        g_rowptr[i] = r;
        g_ofs[i] = r;
    }
    if (i == 0) g_rowptr[NN] = NE;
}

__global__ void k_permute(const int* __restrict__ ei) {
    int e = blockIdx.x * 256 + threadIdx.x;
    if (e < NE) {
        int dst = __ldg(&ei[NE + e]);
        int pos = atomicAdd(&g_ofs[dst], 1);
        g_perm[pos] = e;
    }
}

// ---------------- y = x @ mW[0:64] + mb ----------------
__global__ __launch_bounds__(256) void k_ynode(const float* __restrict__ x,
                                               const float* __restrict__ mW,
                                               const float* __restrict__ mb) {
    __shared__ __align__(16) float sX[32][64];
    __shared__ __align__(16) float sW[64][64];
    int tid = threadIdx.x;
    int node0 = blockIdx.x * 32;
    for (int i = tid; i < 64 * 64; i += 256) sW[i >> 6][i & 63] = mW[i];
    int nl = tid >> 3, f0 = (tid & 7) * 8;
    {
        const float4* xp = reinterpret_cast<const float4*>(x + (u64)(node0 + nl) * DD + f0);
        *reinterpret_cast<float4*>(&sX[nl][f0]) = xp[0];
        *reinterpret_cast<float4*>(&sX[nl][f0 + 4]) = xp[1];
    }
    __syncthreads();
    u64 acc[4] = {0ull, 0ull, 0ull, 0ull};
#pragma unroll
    for (int k = 0; k < 64; k++) {
        u64 ad = f2dup(sX[nl][k]);
        const ulonglong2* wp = reinterpret_cast<const ulonglong2*>(&sW[k][f0]);
        ulonglong2 w0 = wp[0], w1 = wp[1];
        acc[0] = f2fma(ad, w0.x, acc[0]);
        acc[1] = f2fma(ad, w0.y, acc[1]);
        acc[2] = f2fma(ad, w1.x, acc[2]);
        acc[3] = f2fma(ad, w1.y, acc[3]);
    }
    float o[8];
#pragma unroll
    for (int c = 0; c < 4; c++) {
        float2 v = f2unpack(acc[c]);
        o[2 * c] = v.x + mb[f0 + 2 * c];
        o[2 * c + 1] = v.y + mb[f0 + 2 * c + 1];
    }
    float* yp = g_y + (u64)(node0 + nl) * DD + f0;
    *reinterpret_cast<float4*>(yp) = make_float4(o[0], o[1], o[2], o[3]);
    *reinterpret_cast<float4*>(yp + 4) = make_float4(o[4], o[5], o[6], o[7]);
}

// ---------------- k_agg: CSR gather-aggregate, one warp per dst node ----------------
// agg[n] = sum_{e in edges(dst=n)} relu(y[src(e)] + ea[e] @ We)
__global__ __launch_bounds__(256) void k_agg(const float* __restrict__ ea,
                                             const int* __restrict__ ei,
                                             const float* __restrict__ mW) {
    __shared__ float2 sWe[16][32];
    int tid = threadIdx.x;
    for (int i = tid; i < 512; i += 256) {
        int k = i >> 5, l = i & 31;
        sWe[k][l] = *reinterpret_cast<const float2*>(mW + (64 + k) * DD + 2 * l);
    }
    __syncthreads();
    int lane = tid & 31;
    int node = blockIdx.x * 8 + (tid >> 5);
    u64 w[16];
#pragma unroll
    for (int k = 0; k < 16; k++) {
        float2 t = sWe[k][lane];
        w[k] = f2pack(t.x, t.y);
    }
    int b = g_rowptr[node], e_end = g_rowptr[node + 1];
    float accx = 0.f, accy = 0.f;
    for (int e = b; e < e_end; e++) {
        int eo = __ldg(&g_perm[e]);
        int src = __ldg(&ei[eo]);
        const float4* ep = reinterpret_cast<const float4*>(ea + (u64)eo * ECD);
        float4 e0 = __ldg(&ep[0]);
        float4 e1 = __ldg(&ep[1]);
        float4 e2 = __ldg(&ep[2]);
        float4 e3 = __ldg(&ep[3]);
        float2 y = __ldg(reinterpret_cast<const float2*>(g_y + (u64)src * DD + 2 * lane));
        // two chains for ILP
        u64 z0 = 0ull, z1 = 0ull;
        z0 = f2fma(f2dup(e0.x), w[0], z0);
        z1 = f2fma(f2dup(e0.y), w[1], z1);
        z0 = f2fma(f2dup(e0.z), w[2], z0);
        z1 = f2fma(f2dup(e0.w), w[3], z1);
        z0 = f2fma(f2dup(e1.x), w[4], z0);
        z1 = f2fma(f2dup(e1.y), w[5], z1);
        z0 = f2fma(f2dup(e1.z), w[6], z0);
        z1 = f2fma(f2dup(e1.w), w[7], z1);
        z0 = f2fma(f2dup(e2.x), w[8], z0);
        z1 = f2fma(f2dup(e2.y), w[9], z1);
        z0 = f2fma(f2dup(e2.z), w[10], z0);
        z1 = f2fma(f2dup(e2.w), w[11], z1);
        z0 = f2fma(f2dup(e3.x), w[12], z0);
        z1 = f2fma(f2dup(e3.y), w[13], z1);
        z0 = f2fma(f2dup(e3.z), w[14], z0);
        z1 = f2fma(f2dup(e3.w), w[15], z1);
        float2 za = f2unpack(z0), zb = f2unpack(z1);
        accx += fmaxf(y.x + za.x + zb.x, 0.f);
        accy += fmaxf(y.y + za.y + zb.y, 0.f);
    }
    *reinterpret_cast<float2*>(g_agg + (u64)node * DD + 2 * lane) =
        make_float2(accx, accy);
}

// ---------------- update: xo = relu([x, agg] @ uW + ub) ----------------
__global__ __launch_bounds__(128) void k_update(const float* __restrict__ x,
                                                const float* __restrict__ uW,
                                                const float* __restrict__ ub,
                                                float* __restrict__ xo) {
    __shared__ __align__(16) float sIn[16][128];
    __shared__ __align__(16) float sW[128][64];
    int tid = threadIdx.x;
    int node0 = blockIdx.x * 16;
    for (int i = tid; i < 128 * 64; i += 128) sW[i >> 6][i & 63] = uW[i];
    int nl = tid >> 3, f0 = (tid & 7) * 8;
    {
        const float4* xp = reinterpret_cast<const float4*>(x + (u64)(node0 + nl) * DD + f0);
        *reinterpret_cast<float4*>(&sIn[nl][f0]) = xp[0];
        *reinterpret_cast<float4*>(&sIn[nl][f0 + 4]) = xp[1];
        const float4* gp =
            reinterpret_cast<const float4*>(g_agg + (u64)(node0 + nl) * DD + f0);
        *reinterpret_cast<float4*>(&sIn[nl][64 + f0]) = gp[0];
        *reinterpret_cast<float4*>(&sIn[nl][64 + f0 + 4]) = gp[1];
    }
    __syncthreads();
    u64 acc[4] = {0ull, 0ull, 0ull, 0ull};
#pragma unroll 32
    for (int k = 0; k < 128; k++) {
        u64 ad = f2dup(sIn[nl][k]);
        const ulonglong2* wp = reinterpret_cast<const ulonglong2*>(&sW[k][f0]);
        ulonglong2 w0 = wp[0], w1 = wp[1];
        acc[0] = f2fma(ad, w0.x, acc[0]);
        acc[1] = f2fma(ad, w0.y, acc[1]);
        acc[2] = f2fma(ad, w1.x, acc[2]);
        acc[3] = f2fma(ad, w1.y, acc[3]);
    }
    float o[8];
#pragma unroll
    for (int c = 0; c < 4; c++) {
        float2 v = f2unpack(acc[c]);
        o[2 * c] = fmaxf(v.x + ub[f0 + 2 * c], 0.f);
        o[2 * c + 1] = fmaxf(v.y + ub[f0 + 2 * c + 1], 0.f);
    }
    float* op = xo + (u64)(node0 + nl) * DD + f0;
    *reinterpret_cast<float4*>(op) = make_float4(o[0], o[1], o[2], o[3]);
    *reinterpret_cast<float4*>(op + 4) = make_float4(o[4], o[5], o[6], o[7]);
}

// ---------------- node mlp: out = relu(x @ nW1 + nb1) @ nW2 + nb2 ----------------
__global__ __launch_bounds__(128) void k_nodemlp(const float* __restrict__ W1,
                                                 const float* __restrict__ b1,
                                                 const float* __restrict__ W2,
                                                 const float* __restrict__ b2,
                                                 float* __restrict__ out) {
    __shared__ __align__(16) float sW1[64][128];
    __shared__ float sW2[128][3];
    __shared__ __align__(16) float sX[16][64];
    __shared__ float sH[16][128];
    int tid = threadIdx.x;
    int node0 = blockIdx.x * 16;
    for (int i = tid; i < 64 * 128; i += 128) sW1[i >> 7][i & 127] = W1[i];
    sW2[tid][0] = W2[tid * 3 + 0];
    sW2[tid][1] = W2[tid * 3 + 1];
    sW2[tid][2] = W2[tid * 3 + 2];
    {
        int nl = tid >> 3, f0 = (tid & 7) * 8;
        const float4* xp =
            reinterpret_cast<const float4*>(g_x + (u64)(node0 + nl) * DD + f0);
        *reinterpret_cast<float4*>(&sX[nl][f0]) = xp[0];
        *reinterpret_cast<float4*>(&sX[nl][f0 + 4]) = xp[1];
    }
    __syncthreads();
    float bb = b1[tid];
#pragma unroll 4
    for (int n = 0; n < 16; n++) {
        float acc = bb;
#pragma unroll
        for (int k = 0; k < 64; k++) acc += sX[n][k] * sW1[k][tid];
        sH[n][tid] = fmaxf(acc, 0.f);
    }
    __syncthreads();
    if (tid < 48) {
        int node = tid / 3, c = tid % 3;
        float o = b2[c];
#pragma unroll 16
        for (int j = 0; j < 128; j++) o += sH[node][j] * sW2[j][c];
        out[(u64)(node0 + node) * 3 + c] = o;
    }
}

extern "C" void kernel_launch(void* const* d_in, const int* in_sizes, int n_in,
                              void* d_out, int out_size) {
    const float* emb = (const float*)d_in[0];
    const int* edge_index = (const int*)d_in[1];  // JAX x64-disabled: int32
    const float* edge_attr = (const float*)d_in[2];
    const float* Wg1 = (const float*)d_in[3];
    const float* bg1 = (const float*)d_in[4];
    const float* Wg2 = (const float*)d_in[5];
    const float* bg2 = (const float*)d_in[6];
    const float* mW0 = (const float*)d_in[7];
    const float* mb0 = (const float*)d_in[8];
    const float* uW0 = (const float*)d_in[9];
    const float* ub0 = (const float*)d_in[10];
    const float* mW1 = (const float*)d_in[11];
    const float* mb1 = (const float*)d_in[12];
    const float* uW1 = (const float*)d_in[13];
    const float* ub1 = (const float*)d_in[14];
    const float* nW1 = (const float*)d_in[15];
    const float* nb1 = (const float*)d_in[16];
    const float* nW2 = (const float*)d_in[17];
    const float* nb2 = (const float*)d_in[18];
    float* out = (float*)d_out;

    float *p_x, *p_x2;
    cudaGetSymbolAddress((void**)&p_x, g_x);
    cudaGetSymbolAddress((void**)&p_x2, g_x2);

    // CSR build (dst-sorted edge permutation), once per launch
    k_zero_cnt<<<(NN + 255) / 256, 256>>>();
    k_hist<<<(NE + 255) / 256, 256>>>(edge_index);
    k_scan1<<<NSCAN_BLKS, 512>>>();
    k_scan2<<<1, 256>>>();
    k_scan3<<<(NN + 255) / 256, 256>>>();
    k_permute<<<(NE + 255) / 256, 256>>>(edge_index);

    k_mlp1<<<NB, 512>>>(emb, Wg1, bg1);
    k_mlp2<<<G2D / 128, 256>>>(Wg2, bg2);
    // GNN layer 0: g_x -> g_x2
    k_ynode<<<NN / 32, 256>>>(p_x, mW0, mb0);
    k_agg<<<NN / 8, 256>>>(edge_attr, edge_index, mW0);
    k_update<<<NN / 16, 128>>>(p_x, uW0, ub0, p_x2);
    // GNN layer 1: g_x2 -> g_x
    k_ynode<<<NN / 32, 256>>>(p_x2, mW1, mb1);
    k_agg<<<NN / 8, 256>>>(edge_attr, edge_index, mW1);
    k_update<<<NN / 16, 128>>>(p_x2, uW1, ub1, p_x);
    // node MLP
    k_nodemlp<<<NN / 16, 128>>>(nW1, nb1, nW2, nb2, out);
}

// round 5
// speedup vs baseline: 1.5714x; 1.4599x over previous
#include <cuda_runtime.h>

typedef unsigned long long u64;

#define NN 100000
#define NE 1600000
#define EMBD 128
#define G1D 512
#define G2D 64000
#define DD 64
#define ECD 16
#define NB 100
#define NSCAN_BLKS 196

__device__ float g_h[NB * G1D];
__device__ float g_x[NN * DD];
__device__ float g_x2[NN * DD];
__device__ float g_y[NN * DD];
__device__ float g_agg[NN * DD];
__device__ int g_cnt[NN];
__device__ int g_rowptr[NN + 1];
__device__ int g_ofs[NN];
__device__ int g_bsum[NSCAN_BLKS];
__device__ int g_perm[NE];
__device__ int g_srcp[NE];
__device__ float g_eap[(u64)NE * ECD];

__device__ __forceinline__ u64 f2fma(u64 a, u64 b, u64 c) {
    u64 d;
    asm("fma.rn.f32x2 %0, %1, %2, %3;" : "=l"(d) : "l"(a), "l"(b), "l"(c));
    return d;
}
__device__ __forceinline__ u64 f2dup(float x) {
    u64 d;
    asm("mov.b64 %0, {%1, %2};" : "=l"(d) : "f"(x), "f"(x));
    return d;
}
__device__ __forceinline__ u64 f2pack(float x, float y) {
    u64 d;
    asm("mov.b64 %0, {%1, %2};" : "=l"(d) : "f"(x), "f"(y));
    return d;
}
__device__ __forceinline__ float2 f2unpack(u64 d) {
    float2 r;
    asm("mov.b64 {%0, %1}, %2;" : "=f"(r.x), "=f"(r.y) : "l"(d));
    return r;
}

__global__ __launch_bounds__(512) void k_mlp1(const float* __restrict__ emb,
                                              const float* __restrict__ W,
                                              const float* __restrict__ b) {
    __shared__ float sE[EMBD];
    int bid = blockIdx.x, tid = threadIdx.x;
    if (tid < EMBD) sE[tid] = emb[bid * EMBD + tid];
    __syncthreads();
    float acc = 0.f;
#pragma unroll 16
    for (int k = 0; k < EMBD; k++) acc += sE[k] * __ldg(&W[k * G1D + tid]);
    g_h[bid * G1D + tid] = fmaxf(acc + b[tid], 0.f);
}

__global__ __launch_bounds__(256) void k_mlp2(const float* __restrict__ W,
                                              const float* __restrict__ bias) {
    __shared__ __align__(16) u64 sA[16][128];
    __shared__ __align__(16) float sB[16][128];
    const float* h = g_h;
    int tid = threadIdx.x;
    int n0 = blockIdx.x * 128;
    int tx = tid & 15, ty = tid >> 4;
    int mb = ty * 8, cb = tx * 8;
    u64 acc[8][4];
#pragma unroll
    for (int r = 0; r < 8; r++)
#pragma unroll
        for (int c = 0; c < 4; c++) acc[r][c] = 0ull;
    int am = tid >> 1;
    int ak = (tid & 1) * 8;
    int bk = tid >> 4;
    int bn = (tid & 15) * 8;
    for (int k0 = 0; k0 < G1D; k0 += 16) {
        float4 a0 = make_float4(0.f, 0.f, 0.f, 0.f), a1 = a0;
        if (am < NB) {
            const float4* hp = reinterpret_cast<const float4*>(h + am * G1D + k0 + ak);
            a0 = hp[0];
            a1 = hp[1];
        }
        const float4* wp =
            reinterpret_cast<const float4*>(W + (u64)(k0 + bk) * G2D + n0 + bn);
        float4 b0 = wp[0], b1 = wp[1];
        __syncthreads();
        sA[ak + 0][am] = f2dup(a0.x);
        sA[ak + 1][am] = f2dup(a0.y);
        sA[ak + 2][am] = f2dup(a0.z);
        sA[ak + 3][am] = f2dup(a0.w);
        sA[ak + 4][am] = f2dup(a1.x);
        sA[ak + 5][am] = f2dup(a1.y);
        sA[ak + 6][am] = f2dup(a1.z);
        sA[ak + 7][am] = f2dup(a1.w);
        *reinterpret_cast<float4*>(&sB[bk][bn]) = b0;
        *reinterpret_cast<float4*>(&sB[bk][bn + 4]) = b1;
        __syncthreads();
#pragma unroll
        for (int k = 0; k < 16; k++) {
            const ulonglong2* ap = reinterpret_cast<const ulonglong2*>(&sA[k][mb]);
            ulonglong2 av0 = ap[0], av1 = ap[1], av2 = ap[2], av3 = ap[3];
            const ulonglong2* bp = reinterpret_cast<const ulonglong2*>(&sB[k][cb]);
            ulonglong2 bv0 = bp[0], bv1 = bp[1];
            u64 ar[8] = {av0.x, av0.y, av1.x, av1.y, av2.x, av2.y, av3.x, av3.y};
            u64 br[4] = {bv0.x, bv0.y, bv1.x, bv1.y};
#pragma unroll
            for (int r = 0; r < 8; r++)
#pragma unroll
                for (int c = 0; c < 4; c++) acc[r][c] = f2fma(ar[r], br[c], acc[r][c]);
        }
    }
    float2 bs[4];
#pragma unroll
    for (int c = 0; c < 4; c++)
        bs[c] = *reinterpret_cast<const float2*>(bias + n0 + cb + 2 * c);
#pragma unroll
    for (int r = 0; r < 8; r++) {
        int row = mb + r;
        if (row < NB) {
            float* op = g_x + (u64)row * G2D + n0 + cb;
#pragma unroll
            for (int c = 0; c < 4; c++) {
                float2 v = f2unpack(acc[r][c]);
                v.x += bs[c].x;
                v.y += bs[c].y;
                *reinterpret_cast<float2*>(op + 2 * c) = v;
            }
        }
    }
}

__global__ void k_zero_cnt() {
    int i = blockIdx.x * 256 + threadIdx.x;
    if (i < NN) g_cnt[i] = 0;
}
__global__ void k_hist(const int* __restrict__ ei) {
    int e = blockIdx.x * 256 + threadIdx.x;
    if (e < NE) atomicAdd(&g_cnt[__ldg(&ei[NE + e])], 1);
}
__global__ __launch_bounds__(512) void k_scan1() {
    __shared__ int s[512];
    int i = blockIdx.x * 512 + threadIdx.x;
    int v = (i < NN) ? g_cnt[i] : 0;
    s[threadIdx.x] = v;
    __syncthreads();
#pragma unroll
    for (int off = 1; off < 512; off <<= 1) {
        int t = (threadIdx.x >= off) ? s[threadIdx.x - off] : 0;
        __syncthreads();
        s[threadIdx.x] += t;
        __syncthreads();
    }
    if (i < NN) g_rowptr[i] = s[threadIdx.x] - v;
    if (threadIdx.x == 511) g_bsum[blockIdx.x] = s[511];
}
__global__ __launch_bounds__(256) void k_scan2() {
    __shared__ int s[256];
    int tid = threadIdx.x;
    int v = (tid < NSCAN_BLKS) ? g_bsum[tid] : 0;
    s[tid] = v;
    __syncthreads();
#pragma unroll
    for (int off = 1; off < 256; off <<= 1) {
        int t = (tid >= off) ? s[tid - off] : 0;
        __syncthreads();
        s[tid] += t;
        __syncthreads();
    }
    if (tid < NSCAN_BLKS) g_bsum[tid] = s[tid] - v;
}
__global__ void k_scan3() {
    int i = blockIdx.x * 256 + threadIdx.x;
    if (i < NN) {
        int r = g_rowptr[i] + g_bsum[i >> 9];
        g_rowptr[i] = r;
        g_ofs[i] = r;
    }
    if (i == 0) g_rowptr[NN] = NE;
}
__global__ void k_permute(const int* __restrict__ ei) {
    int e = blockIdx.x * 256 + threadIdx.x;
    if (e < NE) {
        int dst = __ldg(&ei[NE + e]);
        int pos = atomicAdd(&g_ofs[dst], 1);
        g_perm[pos] = e;
    }
}
__global__ __launch_bounds__(256) void k_gatherperm(const int* __restrict__ ei,
                                                    const float* __restrict__ ea) {
    int tid = threadIdx.x;
    int t = tid & 3;
    int pos = blockIdx.x * 64 + (tid >> 2);
    int eo = __ldg(&g_perm[pos]);
    if (t == 0) g_srcp[pos] = __ldg(&ei[eo]);
    float4 v = __ldg(reinterpret_cast<const float4*>(ea) + (u64)eo * 4 + t);
    reinterpret_cast<float4*>(g_eap)[(u64)pos * 4 + t] = v;
}

__global__ __launch_bounds__(128) void k_ynode(const float* __restrict__ x,
                                               const float* __restrict__ mW,
                                               const float* __restrict__ mb) {
    __shared__ float sX[64][65];
    __shared__ float sW[64][64];
    int tid = threadIdx.x;
    int node0 = blockIdx.x * 64;
    for (int i = tid; i < 64 * 64; i += 128) sW[i >> 6][i & 63] = mW[i];
    for (int i = tid; i < 64 * 64; i += 128) {
        int n = i >> 6, c = i & 63;
        int nn = node0 + n;
        if (nn >= NN) nn = NN - 1;
        sX[n][c] = x[(u64)nn * DD + c];
    }
    __syncthreads();
    int f0 = (tid & 7) * 8;
    int n0 = (tid >> 3) * 4;
    u64 acc[4][4];
#pragma unroll
    for (int j = 0; j < 4; j++)
#pragma unroll
        for (int c = 0; c < 4; c++) acc[j][c] = 0ull;
#pragma unroll 8
    for (int k = 0; k < 64; k++) {
        ulonglong2 w01 = *reinterpret_cast<const ulonglong2*>(&sW[k][f0]);
        ulonglong2 w23 = *reinterpret_cast<const ulonglong2*>(&sW[k][f0 + 4]);
#pragma unroll
        for (int j = 0; j < 4; j++) {
            u64 a = f2dup(sX[n0 + j][k]);
            acc[j][0] = f2fma(a, w01.x, acc[j][0]);
            acc[j][1] = f2fma(a, w01.y, acc[j][1]);
            acc[j][2] = f2fma(a, w23.x, acc[j][2]);
            acc[j][3] = f2fma(a, w23.y, acc[j][3]);
        }
    }
    float2 bv[4];
#pragma unroll
    for (int c = 0; c < 4; c++)
        bv[c] = *reinterpret_cast<const float2*>(mb + f0 + 2 * c);
#pragma unroll
    for (int j = 0; j < 4; j++) {
        int nn = node0 + n0 + j;
        if (nn < NN) {
            float o[8];
#pragma unroll
            for (int c = 0; c < 4; c++) {
                float2 v = f2unpack(acc[j][c]);
                o[2 * c] = v.x + bv[c].x;
                o[2 * c + 1] = v.y + bv[c].y;
            }
            float* yp = g_y + (u64)nn * DD + f0;
            *reinterpret_cast<float4*>(yp) = make_float4(o[0], o[1], o[2], o[3]);
            *reinterpret_cast<float4*>(yp + 4) = make_float4(o[4], o[5], o[6], o[7]);
        }
    }
}

__global__ __launch_bounds__(256) void k_agg(const float* __restrict__ mW) {
    __shared__ float2 sWe[16][32];
    int tid = threadIdx.x;
    for (int i = tid; i < 512; i += 256) {
        int k = i >> 5, l = i & 31;
        sWe[k][l] = *reinterpret_cast<const float2*>(mW + (64 + k) * DD + 2 * l);
    }
    __syncthreads();
    int lane = tid & 31;
    int node = blockIdx.x * 8 + (tid >> 5);
    u64 w[16];
#pragma unroll
    for (int k = 0; k < 16; k++) {
        float2 t = sWe[k][lane];
        w[k] = f2pack(t.x, t.y);
    }
    int e = g_rowptr[node], e_end = g_rowptr[node + 1];
    float accx = 0.f, accy = 0.f;
    for (; e + 2 <= e_end; e += 2) {
        int s0 = __ldg(&g_srcp[e]);
        int s1 = __ldg(&g_srcp[e + 1]);
        const float4* p = reinterpret_cast<const float4*>(g_eap + (u64)e * ECD);
        float4 a0 = __ldg(p + 0), a1 = __ldg(p + 1), a2 = __ldg(p + 2), a3 = __ldg(p + 3);
        float4 c0 = __ldg(p + 4), c1 = __ldg(p + 5), c2 = __ldg(p + 6), c3 = __ldg(p + 7);
        float2 y0 = __ldg(reinterpret_cast<const float2*>(g_y + (u64)s0 * DD) + lane);
        float2 y1 = __ldg(reinterpret_cast<const float2*>(g_y + (u64)s1 * DD) + lane);
        {
            u64 z0 = 0ull, z1 = 0ull;
            z0 = f2fma(f2dup(a0.x), w[0], z0);  z1 = f2fma(f2dup(a0.y), w[1], z1);
            z0 = f2fma(f2dup(a0.z), w[2], z0);  z1 = f2fma(f2dup(a0.w), w[3], z1);
            z0 = f2fma(f2dup(a1.x), w[4], z0);  z1 = f2fma(f2dup(a1.y), w[5], z1);
            z0 = f2fma(f2dup(a1.z), w[6], z0);  z1 = f2fma(f2dup(a1.w), w[7], z1);
            z0 = f2fma(f2dup(a2.x), w[8], z0);  z1 = f2fma(f2dup(a2.y), w[9], z1);
            z0 = f2fma(f2dup(a2.z), w[10], z0); z1 = f2fma(f2dup(a2.w), w[11], z1);
            z0 = f2fma(f2dup(a3.x), w[12], z0); z1 = f2fma(f2dup(a3.y), w[13], z1);
            z0 = f2fma(f2dup(a3.z), w[14], z0); z1 = f2fma(f2dup(a3.w), w[15], z1);
            float2 za = f2unpack(z0), zb = f2unpack(z1);
            accx += fmaxf(y0.x + za.x + zb.x, 0.f);
            accy += fmaxf(y0.y + za.y + zb.y, 0.f);
        }
        {
            u64 z0 = 0ull, z1 = 0ull;
            z0 = f2fma(f2dup(c0.x), w[0], z0);  z1 = f2fma(f2dup(c0.y), w[1], z1);
            z0 = f2fma(f2dup(c0.z), w[2], z0);  z1 = f2fma(f2dup(c0.w), w[3], z1);
            z0 = f2fma(f2dup(c1.x), w[4], z0);  z1 = f2fma(f2dup(c1.y), w[5], z1);
            z0 = f2fma(f2dup(c1.z), w[6], z0);  z1 = f2fma(f2dup(c1.w), w[7], z1);
            z0 = f2fma(f2dup(c2.x), w[8], z0);  z1 = f2fma(f2dup(c2.y), w[9], z1);
            z0 = f2fma(f2dup(c2.z), w[10], z0); z1 = f2fma(f2dup(c2.w), w[11], z1);
            z0 = f2fma(f2dup(c3.x), w[12], z0); z1 = f2fma(f2dup(c3.y), w[13], z1);
            z0 = f2fma(f2dup(c3.z), w[14], z0); z1 = f2fma(f2dup(c3.w), w[15], z1);
            float2 za = f2unpack(z0), zb = f2unpack(z1);
            accx += fmaxf(y1.x + za.x + zb.x, 0.f);
            accy += fmaxf(y1.y + za.y + zb.y, 0.f);
        }
    }
    if (e < e_end) {
        int s0 = __ldg(&g_srcp[e]);
        const float4* p = reinterpret_cast<const float4*>(g_eap + (u64)e * ECD);
        float4 a0 = __ldg(p + 0), a1 = __ldg(p + 1), a2 = __ldg(p + 2), a3 = __ldg(p + 3);
        float2 y0 = __ldg(reinterpret_cast<const float2*>(g_y + (u64)s0 * DD) + lane);
        u64 z0 = 0ull, z1 = 0ull;
        z0 = f2fma(f2dup(a0.x), w[0], z0);  z1 = f2fma(f2dup(a0.y), w[1], z1);
        z0 = f2fma(f2dup(a0.z), w[2], z0);  z1 = f2fma(f2dup(a0.w), w[3], z1);
        z0 = f2fma(f2dup(a1.x), w[4], z0);  z1 = f2fma(f2dup(a1.y), w[5], z1);
        z0 = f2fma(f2dup(a1.z), w[6], z0);  z1 = f2fma(f2dup(a1.w), w[7], z1);
        z0 = f2fma(f2dup(a2.x), w[8], z0);  z1 = f2fma(f2dup(a2.y), w[9], z1);
        z0 = f2fma(f2dup(a2.z), w[10], z0); z1 = f2fma(f2dup(a2.w), w[11], z1);
        z0 = f2fma(f2dup(a3.x), w[12], z0); z1 = f2fma(f2dup(a3.y), w[13], z1);
        z0 = f2fma(f2dup(a3.z), w[14], z0); z1 = f2fma(f2dup(a3.w), w[15], z1);
        float2 za = f2unpack(z0), zb = f2unpack(z1);
        accx += fmaxf(y0.x + za.x + zb.x, 0.f);
        accy += fmaxf(y0.y + za.y + zb.y, 0.f);
    }
    *reinterpret_cast<float2*>(g_agg + (u64)node * DD + 2 * lane) =
        make_float2(accx, accy);
}

#define UPD_SMEM (128 * 130 * 4 + 128 * 64 * 4)
__global__ __launch_bounds__(256) void k_update(const float* __restrict__ x,
                                                const float* __restrict__ uW,
                                                const float* __restrict__ ub,
                                                float* __restrict__ xo) {
    extern __shared__ float us[];
    float(*sIn)[130] = reinterpret_cast<float(*)[130]>(us);
    float(*sW)[64] = reinterpret_cast<float(*)[64]>(us + 128 * 130);
    int tid = threadIdx.x;
    int node0 = blockIdx.x * 128;
    for (int i = tid; i < 128 * 64; i += 256) sW[i >> 6][i & 63] = uW[i];
    for (int i = tid; i < 128 * 128; i += 256) {
        int n = i >> 7, c = i & 127;
        int nn = node0 + n;
        if (nn >= NN) nn = NN - 1;
        float v = (c < 64) ? x[(u64)nn * DD + c] : g_agg[(u64)nn * DD + c - 64];
        sIn[n][c] = v;
    }
    __syncthreads();
    int f0 = (tid & 7) * 8;
    int n0 = (tid >> 3) * 4;
    u64 acc[4][4];
#pragma unroll
    for (int j = 0; j < 4; j++)
#pragma unroll
        for (int c = 0; c < 4; c++) acc[j][c] = 0ull;
#pragma unroll 8
    for (int k = 0; k < 128; k++) {
        ulonglong2 w01 = *reinterpret_cast<const ulonglong2*>(&sW[k][f0]);
        ulonglong2 w23 = *reinterpret_cast<const ulonglong2*>(&sW[k][f0 + 4]);
#pragma unroll
        for (int j = 0; j < 4; j++) {
            u64 a = f2dup(sIn[n0 + j][k]);
            acc[j][0] = f2fma(a, w01.x, acc[j][0]);
            acc[j][1] = f2fma(a, w01.y, acc[j][1]);
            acc[j][2] = f2fma(a, w23.x, acc[j][2]);
            acc[j][3] = f2fma(a, w23.y, acc[j][3]);
        }
    }
    float2 bv[4];
#pragma unroll
    for (int c = 0; c < 4; c++)
        bv[c] = *reinterpret_cast<const float2*>(ub + f0 + 2 * c);
#pragma unroll
    for (int j = 0; j < 4; j++) {
        int nn = node0 + n0 + j;
        if (nn < NN) {
            float o[8];
#pragma unroll
            for (int c = 0; c < 4; c++) {
                float2 v = f2unpack(acc[j][c]);
                o[2 * c] = fmaxf(v.x + bv[c].x, 0.f);
                o[2 * c + 1] = fmaxf(v.y + bv[c].y, 0.f);
            }
            float* op = xo + (u64)nn * DD + f0;
            *reinterpret_cast<float4*>(op) = make_float4(o[0], o[1], o[2], o[3]);
            *reinterpret_cast<float4*>(op + 4) = make_float4(o[4], o[5], o[6], o[7]);
        }
    }
}

#define NM_SMEM (64 * 128 * 4 + 64 * 65 * 4 + 64 * 130 * 4 + 128 * 4 * 4)
__global__ __launch_bounds__(256) void k_nodemlp(const float* __restrict__ W1,
                                                 const float* __restrict__ b1,
                                                 const float* __restrict__ W2,
                                                 const float* __restrict__ b2,
                                                 float* __restrict__ out) {
    extern __shared__ float nsm[];
    float(*sW1)[128] = reinterpret_cast<float(*)[128]>(nsm);
    float(*sX)[65] = reinterpret_cast<float(*)[65]>(nsm + 64 * 128);
    float(*sH)[130] = reinterpret_cast<float(*)[130]>(nsm + 64 * 128 + 64 * 65);
    float(*sW2)[4] =
        reinterpret_cast<float(*)[4]>(nsm + 64 * 128 + 64 * 65 + 64 * 130);
    int tid = threadIdx.x;
    int node0 = blockIdx.x * 64;
    for (int i = tid; i < 64 * 128; i += 256) sW1[i >> 7][i & 127] = W1[i];
    if (tid < 128) {
        sW2[tid][0] = W2[tid * 3 + 0];
        sW2[tid][1] = W2[tid * 3 + 1];
        sW2[tid][2] = W2[tid * 3 + 2];
    }
    for (int i = tid; i < 64 * 64; i += 256) {
        int n = i >> 6, c = i & 63;
        int nn = node0 + n;
        if (nn >= NN) nn = NN - 1;
        sX[n][c] = g_x[(u64)nn * DD + c];
    }
    __syncthreads();
    int f0 = (tid & 15) * 8;
    int n0 = (tid >> 4) * 4;
    u64 acc[4][4];
#pragma unroll
    for (int j = 0; j < 4; j++)
#pragma unroll
        for (int c = 0; c < 4; c++) acc[j][c] = 0ull;
#pragma unroll 8
    for (int k = 0; k < 64; k++) {
        ulonglong2 w01 = *reinterpret_cast<const ulonglong2*>(&sW1[k][f0]);
        ulonglong2 w23 = *reinterpret_cast<const ulonglong2*>(&sW1[k][f0 + 4]);
#pragma unroll
        for (int j = 0; j < 4; j++) {
            u64 a = f2dup(sX[n0 + j][k]);
            acc[j][0] = f2fma(a, w01.x, acc[j][0]);
            acc[j][1] = f2fma(a, w01.y, acc[j][1]);
            acc[j][2] = f2fma(a, w23.x, acc[j][2]);
            acc[j][3] = f2fma(a, w23.y, acc[j][3]);
        }
    }
    float2 bv[4];
#pragma unroll
    for (int c = 0; c < 4; c++)
        bv[c] = *reinterpret_cast<const float2*>(b1 + f0 + 2 * c);
#pragma unroll
    for (int j = 0; j < 4; j++) {
#pragma unroll
        for (int c = 0; c < 4; c++) {
            float2 v = f2unpack(acc[j][c]);
            sH[n0 + j][f0 + 2 * c] = fmaxf(v.x + bv[c].x, 0.f);
            sH[n0 + j][f0 + 2 * c + 1] = fmaxf(v.y + bv[c].y, 0.f);
        }
    }
    __syncthreads();
    if (tid < 192) {
        int node = tid / 3, c = tid % 3;
        int nn = node0 + node;
        if (nn < NN) {
            float o = b2[c];
#pragma unroll 16
            for (int j = 0; j < 128; j++) o += sH[node][j] * sW2[j][c];
            out[(u64)nn * 3 + c] = o;
        }
    }
}

extern "C" void kernel_launch(void* const* d_in, const int* in_sizes, int n_in,
                              void* d_out, int out_size) {
    const float* emb = (const float*)d_in[0];
    const int* edge_index = (const int*)d_in[1];
    const float* edge_attr = (const float*)d_in[2];
    const float* Wg1 = (const float*)d_in[3];
    const float* bg1 = (const float*)d_in[4];
    const float* Wg2 = (const float*)d_in[5];
    const float* bg2 = (const float*)d_in[6];
    const float* mW0 = (const float*)d_in[7];
    const float* mb0 = (const float*)d_in[8];
    const float* uW0 = (const float*)d_in[9];
    const float* ub0 = (const float*)d_in[10];
    const float* mW1 = (const float*)d_in[11];
    const float* mb1 = (const float*)d_in[12];
    const float* uW1 = (const float*)d_in[13];
    const float* ub1 = (const float*)d_in[14];
    const float* nW1 = (const float*)d_in[15];
    const float* nb1 = (const float*)d_in[16];
    const float* nW2 = (const float*)d_in[17];
    const float* nb2 = (const float*)d_in[18];
    float* out = (float*)d_out;

    float *p_x, *p_x2;
    cudaGetSymbolAddress((void**)&p_x, g_x);
    cudaGetSymbolAddress((void**)&p_x2, g_x2);

    cudaFuncSetAttribute(k_update, cudaFuncAttributeMaxDynamicSharedMemorySize,
                         UPD_SMEM);
    cudaFuncSetAttribute(k_nodemlp, cudaFuncAttributeMaxDynamicSharedMemorySize,
                         NM_SMEM);

    k_zero_cnt<<<(NN + 255) / 256, 256>>>();
    k_hist<<<(NE + 255) / 256, 256>>>(edge_index);
    k_scan1<<<NSCAN_BLKS, 512>>>();
    k_scan2<<<1, 256>>>();
    k_scan3<<<(NN + 255) / 256, 256>>>();
    k_permute<<<(NE + 255) / 256, 256>>>(edge_index);
    k_gatherperm<<<NE / 64, 256>>>(edge_index, edge_attr);

    k_mlp1<<<NB, 512>>>(emb, Wg1, bg1);
    k_mlp2<<<G2D / 128, 256>>>(Wg2, bg2);
    k_ynode<<<(NN + 63) / 64, 128>>>(p_x, mW0, mb0);
    k_agg<<<NN / 8, 256>>>(mW0);
    k_update<<<(NN + 127) / 128, 256, UPD_SMEM>>>(p_x, uW0, ub0, p_x2);
    k_ynode<<<(NN + 63) / 64, 128>>>(p_x2, mW1, mb1);
    k_agg<<<NN / 8, 256>>>(mW1);
    k_update<<<(NN + 127) / 128, 256, UPD_SMEM>>>(p_x2, uW1, ub1, p_x);
    k_nodemlp<<<(NN + 63) / 64, 256, NM_SMEM>>>(nW1, nb1, nW2, nb2, out);
}